// round 15
// baseline (speedup 1.0000x reference)
#include <cuda_runtime.h>
#include <cuda_bf16.h>
#include <math.h>

// Problem constants
#define S 2048
#define B 32
#define H 1024
#define R (S * B)          // 65536 rows of hidden_sequence, row r = s*B + b

// -------- scratch (no cudaMalloc allowed) --------
__device__ float g_energy[R];        // energy (S,B) row-major == index r; reused as attn
__device__ float g_h2[B * H];        // b1[k] + b2[k] + hidden[b,:]·W2[k,:]

// ---------------------------------------------------------------------------
// Kernel Z: zero the energy scratch (it is accumulated via atomicAdd)
// ---------------------------------------------------------------------------
__global__ void kz_zero_energy() {
    int i = blockIdx.x * blockDim.x + threadIdx.x;
    if (i < R) g_energy[i] = 0.0f;
}

// ---------------------------------------------------------------------------
// Kernel 0: h2[b,k] = b1[k] + b2[k] + sum_h hidden[b,h] * W2[k,h]
// one warp per (b,k) output; coalesced float4 reads along h
// ---------------------------------------------------------------------------
__global__ void k_h2(const float* __restrict__ hidden,
                     const float* __restrict__ W2,
                     const float* __restrict__ b1,
                     const float* __restrict__ b2) {
    int gw   = (blockIdx.x * blockDim.x + threadIdx.x) >> 5;  // global warp id
    int lane = threadIdx.x & 31;
    if (gw >= B * H) return;
    int b = gw >> 10;          // / H
    int k = gw & (H - 1);      // % H

    const float4* hp = (const float4*)(hidden + (size_t)b * H);
    const float4* wp = (const float4*)(W2 + (size_t)k * H);
    float acc = 0.0f;
    #pragma unroll
    for (int i = lane; i < H / 4; i += 32) {
        float4 hv = hp[i];
        float4 wv = wp[i];
        acc += hv.x * wv.x + hv.y * wv.y + hv.z * wv.z + hv.w * wv.w;
    }
    #pragma unroll
    for (int o = 16; o; o >>= 1) acc += __shfl_xor_sync(0xffffffffu, acc, o);
    if (lane == 0) g_h2[gw] = acc + b1[k] + b2[k];
}

// ---------------------------------------------------------------------------
// Kernel 1: fused energy GEMM
//   pre[r,k] = sum_h hs[r,h] * W1[k,h]      (r = s*B+b, both operands K-major)
//   energy[r] += sum_{k in tile} v[k] * tanh(pre[r,k] + h2[r%B, k])
// 128x128 tile, BK=16, 256 threads, 8x8 micro-tiles.
// grid.x = k-tiles (8), grid.y = row-tiles (512) so concurrent CTAs share hs in L2.
// ---------------------------------------------------------------------------
#define BM 128
#define BN 128
#define BK 16
#define TM 8
#define TN 8

__global__ __launch_bounds__(256, 2)
void k_energy_gemm(const float* __restrict__ hs,
                   const float* __restrict__ W1,
                   const float* __restrict__ v) {
    __shared__ float As[BK][BM];
    __shared__ float Bs[BK][BN];
    __shared__ float rowsum[BM];

    const int tid = threadIdx.x;
    const int n0  = blockIdx.x * BN;   // k-tile
    const int m0  = blockIdx.y * BM;   // row-tile
    const int tx  = tid & 15;
    const int ty  = tid >> 4;

    float acc[TM][TN];
    #pragma unroll
    for (int i = 0; i < TM; ++i)
        #pragma unroll
        for (int j = 0; j < TN; ++j) acc[i][j] = 0.0f;

    for (int h0 = 0; h0 < H; h0 += BK) {
        // load hs tile (transpose to [k][m]); 512 float4s, 2 per thread
        #pragma unroll
        for (int i = 0; i < 2; ++i) {
            int j   = tid + i * 256;          // 0..511
            int row = j >> 2;                 // 0..127
            int c4  = (j & 3) * 4;            // 0,4,8,12
            float4 t = *(const float4*)&hs[(size_t)(m0 + row) * H + h0 + c4];
            As[c4 + 0][row] = t.x; As[c4 + 1][row] = t.y;
            As[c4 + 2][row] = t.z; As[c4 + 3][row] = t.w;
        }
        // load W1 tile (transpose to [k][n])
        #pragma unroll
        for (int i = 0; i < 2; ++i) {
            int j   = tid + i * 256;
            int row = j >> 2;
            int c4  = (j & 3) * 4;
            float4 t = *(const float4*)&W1[(size_t)(n0 + row) * H + h0 + c4];
            Bs[c4 + 0][row] = t.x; Bs[c4 + 1][row] = t.y;
            Bs[c4 + 2][row] = t.z; Bs[c4 + 3][row] = t.w;
        }
        __syncthreads();

        #pragma unroll
        for (int kk = 0; kk < BK; ++kk) {
            float a[TM], bb[TN];
            #pragma unroll
            for (int i = 0; i < TM; ++i) a[i] = As[kk][ty * TM + i];
            #pragma unroll
            for (int j = 0; j < TN; ++j) bb[j] = Bs[kk][tx * TN + j];
            #pragma unroll
            for (int i = 0; i < TM; ++i)
                #pragma unroll
                for (int j = 0; j < TN; ++j)
                    acc[i][j] = fmaf(a[i], bb[j], acc[i][j]);
        }
        __syncthreads();
    }

    // epilogue: v-weighted tanh reduction over this block's k-range
    if (tid < BM) rowsum[tid] = 0.0f;
    __syncthreads();

    #pragma unroll
    for (int i = 0; i < TM; ++i) {
        int m = ty * TM + i;
        int r = m0 + m;
        int b = r & (B - 1);               // r % B, B = 32
        float p = 0.0f;
        #pragma unroll
        for (int j = 0; j < TN; ++j) {
            int k = n0 + tx * TN + j;
            p += v[k] * tanhf(acc[i][j] + g_h2[b * H + k]);
        }
        atomicAdd(&rowsum[m], p);
    }
    __syncthreads();
    if (tid < BM) atomicAdd(&g_energy[m0 + tid], rowsum[tid]);
}

// ---------------------------------------------------------------------------
// Kernel 2: masked softmax over S per batch column; also zeroes d_out row
// one block (256 threads) per b
// ---------------------------------------------------------------------------
__global__ void k_softmax(const int* __restrict__ mask, float* __restrict__ out) {
    __shared__ float buf[S];
    __shared__ float redm[8];
    __shared__ float reds[8];

    const int b   = blockIdx.x;
    const int tid = threadIdx.x;

    float lmax = -3.4e38f;
    for (int s = tid; s < S; s += 256) {
        float e = mask[s * B + b] ? g_energy[s * B + b] : -1e10f;
        buf[s] = e;
        lmax = fmaxf(lmax, e);
    }
    #pragma unroll
    for (int o = 16; o; o >>= 1) lmax = fmaxf(lmax, __shfl_xor_sync(0xffffffffu, lmax, o));
    if ((tid & 31) == 0) redm[tid >> 5] = lmax;
    __syncthreads();
    if (tid == 0) {
        float m = redm[0];
        #pragma unroll
        for (int w = 1; w < 8; ++w) m = fmaxf(m, redm[w]);
        redm[0] = m;
    }
    __syncthreads();
    const float gmax = redm[0];

    float lsum = 0.0f;
    for (int s = tid; s < S; s += 256) {
        float ex = __expf(buf[s] - gmax);
        buf[s] = ex;
        lsum += ex;
    }
    #pragma unroll
    for (int o = 16; o; o >>= 1) lsum += __shfl_xor_sync(0xffffffffu, lsum, o);
    if ((tid & 31) == 0) reds[tid >> 5] = lsum;
    __syncthreads();
    if (tid == 0) {
        float sum = 0.0f;
        #pragma unroll
        for (int w = 0; w < 8; ++w) sum += reds[w];
        reds[0] = 1.0f / sum;
    }
    __syncthreads();
    const float inv = reds[0];

    for (int s = tid; s < S; s += 256)
        g_energy[s * B + b] = buf[s] * inv;       // now holds attn

    // zero this batch's output row (d_out is poisoned; k_ctx accumulates atomically)
    for (int i = tid; i < H; i += 256) out[b * H + i] = 0.0f;
}

// ---------------------------------------------------------------------------
// Kernel 3: context[b,h] = sum_s attn[s,b] * hs[s,b,h]
// grid (B, H/256, S_splits=8); atomicAdd into out
// ---------------------------------------------------------------------------
__global__ void k_ctx(const float* __restrict__ hs, float* __restrict__ out) {
    const int b  = blockIdx.x;
    const int h  = blockIdx.y * 256 + threadIdx.x;
    const int s0 = blockIdx.z * (S / 8);

    float acc = 0.0f;
    #pragma unroll 8
    for (int s = s0; s < s0 + S / 8; ++s) {
        float a = g_energy[s * B + b];
        acc = fmaf(a, __ldg(&hs[((size_t)s * B + b) * H + h]), acc);
    }
    atomicAdd(&out[b * H + h], acc);
}

// ---------------------------------------------------------------------------
// launch
// inputs: 0 hidden (1,B,H) f32 | 1 hidden_sequence (S,B,H) f32 | 2 input_masks (S,B) int32
//         3 W1 (H,H) f32 | 4 b1 (H) f32 | 5 W2 (H,H) f32 | 6 b2 (H) f32 | 7 v (H) f32
// output: context (1,B,H) f32
// ---------------------------------------------------------------------------
extern "C" void kernel_launch(void* const* d_in, const int* in_sizes, int n_in,
                              void* d_out, int out_size) {
    const float* hidden = (const float*)d_in[0];
    const float* hs     = (const float*)d_in[1];
    const int*   mask   = (const int*)d_in[2];   // bool promoted to int32 (assumed)
    const float* W1     = (const float*)d_in[3];
    const float* b1     = (const float*)d_in[4];
    const float* W2     = (const float*)d_in[5];
    const float* b2     = (const float*)d_in[6];
    const float* v      = (const float*)d_in[7];
    float*       out    = (float*)d_out;

    // 1) zero energy accumulator
    kz_zero_energy<<<R / 256, 256>>>();

    // 2) h2 = hidden·W2^T + b1 + b2  (one warp per output, 8 warps/block)
    k_h2<<<(B * H) / 8, 256>>>(hidden, W2, b1, b2);

    // 3) fused energy GEMM: grid.x = k-tiles, grid.y = row-tiles
    dim3 g1(H / BN, R / BM);
    k_energy_gemm<<<g1, 256>>>(hs, W1, v);

    // 4) masked softmax per batch + zero out
    k_softmax<<<B, 256>>>(mask, out);

    // 5) context accumulation
    dim3 g3(B, H / 256, 8);
    k_ctx<<<g3, 256>>>(hs, out);
}

// round 16
// speedup vs baseline: 1.0001x; 1.0001x over previous
#include <cuda_runtime.h>
#include <cuda_bf16.h>
#include <math.h>

// Problem constants
#define S 2048
#define B 32
#define H 1024
#define R (S * B)          // 65536 rows of hidden_sequence, row r = s*B + b

// -------- scratch (no cudaMalloc allowed) --------
__device__ float g_energy[R];        // energy (S,B) row-major == index r; reused as attn
__device__ float g_h2[B * H];        // b1[k] + b2[k] + hidden[b,:]·W2[k,:]

// ---------------------------------------------------------------------------
// Kernel Z: zero the energy scratch (it is accumulated via atomicAdd)
// ---------------------------------------------------------------------------
__global__ void kz_zero_energy() {
    int i = blockIdx.x * blockDim.x + threadIdx.x;
    if (i < R) g_energy[i] = 0.0f;
}

// ---------------------------------------------------------------------------
// Kernel 0: h2[b,k] = b1[k] + b2[k] + sum_h hidden[b,h] * W2[k,h]
// one warp per (b,k) output; coalesced float4 reads along h
// ---------------------------------------------------------------------------
__global__ void k_h2(const float* __restrict__ hidden,
                     const float* __restrict__ W2,
                     const float* __restrict__ b1,
                     const float* __restrict__ b2) {
    int gw   = (blockIdx.x * blockDim.x + threadIdx.x) >> 5;  // global warp id
    int lane = threadIdx.x & 31;
    if (gw >= B * H) return;
    int b = gw >> 10;          // / H
    int k = gw & (H - 1);      // % H

    const float4* hp = (const float4*)(hidden + (size_t)b * H);
    const float4* wp = (const float4*)(W2 + (size_t)k * H);
    float acc = 0.0f;
    #pragma unroll
    for (int i = lane; i < H / 4; i += 32) {
        float4 hv = hp[i];
        float4 wv = wp[i];
        acc += hv.x * wv.x + hv.y * wv.y + hv.z * wv.z + hv.w * wv.w;
    }
    #pragma unroll
    for (int o = 16; o; o >>= 1) acc += __shfl_xor_sync(0xffffffffu, acc, o);
    if (lane == 0) g_h2[gw] = acc + b1[k] + b2[k];
}

// ---------------------------------------------------------------------------
// Kernel 1: fused energy GEMM
//   pre[r,k] = sum_h hs[r,h] * W1[k,h]      (r = s*B+b, both operands K-major)
//   energy[r] += sum_{k in tile} v[k] * tanh(pre[r,k] + h2[r%B, k])
// 128x128 tile, BK=16, 256 threads, 8x8 micro-tiles.
// grid.x = k-tiles (8), grid.y = row-tiles (512) so concurrent CTAs share hs in L2.
// ---------------------------------------------------------------------------
#define BM 128
#define BN 128
#define BK 16
#define TM 8
#define TN 8

__global__ __launch_bounds__(256, 2)
void k_energy_gemm(const float* __restrict__ hs,
                   const float* __restrict__ W1,
                   const float* __restrict__ v) {
    __shared__ float As[BK][BM];
    __shared__ float Bs[BK][BN];
    __shared__ float rowsum[BM];

    const int tid = threadIdx.x;
    const int n0  = blockIdx.x * BN;   // k-tile
    const int m0  = blockIdx.y * BM;   // row-tile
    const int tx  = tid & 15;
    const int ty  = tid >> 4;

    float acc[TM][TN];
    #pragma unroll
    for (int i = 0; i < TM; ++i)
        #pragma unroll
        for (int j = 0; j < TN; ++j) acc[i][j] = 0.0f;

    for (int h0 = 0; h0 < H; h0 += BK) {
        // load hs tile (transpose to [k][m]); 512 float4s, 2 per thread
        #pragma unroll
        for (int i = 0; i < 2; ++i) {
            int j   = tid + i * 256;          // 0..511
            int row = j >> 2;                 // 0..127
            int c4  = (j & 3) * 4;            // 0,4,8,12
            float4 t = *(const float4*)&hs[(size_t)(m0 + row) * H + h0 + c4];
            As[c4 + 0][row] = t.x; As[c4 + 1][row] = t.y;
            As[c4 + 2][row] = t.z; As[c4 + 3][row] = t.w;
        }
        // load W1 tile (transpose to [k][n])
        #pragma unroll
        for (int i = 0; i < 2; ++i) {
            int j   = tid + i * 256;
            int row = j >> 2;
            int c4  = (j & 3) * 4;
            float4 t = *(const float4*)&W1[(size_t)(n0 + row) * H + h0 + c4];
            Bs[c4 + 0][row] = t.x; Bs[c4 + 1][row] = t.y;
            Bs[c4 + 2][row] = t.z; Bs[c4 + 3][row] = t.w;
        }
        __syncthreads();

        #pragma unroll
        for (int kk = 0; kk < BK; ++kk) {
            float a[TM], bb[TN];
            #pragma unroll
            for (int i = 0; i < TM; ++i) a[i] = As[kk][ty * TM + i];
            #pragma unroll
            for (int j = 0; j < TN; ++j) bb[j] = Bs[kk][tx * TN + j];
            #pragma unroll
            for (int i = 0; i < TM; ++i)
                #pragma unroll
                for (int j = 0; j < TN; ++j)
                    acc[i][j] = fmaf(a[i], bb[j], acc[i][j]);
        }
        __syncthreads();
    }

    // epilogue: v-weighted tanh reduction over this block's k-range
    if (tid < BM) rowsum[tid] = 0.0f;
    __syncthreads();

    #pragma unroll
    for (int i = 0; i < TM; ++i) {
        int m = ty * TM + i;
        int r = m0 + m;
        int b = r & (B - 1);               // r % B, B = 32
        float p = 0.0f;
        #pragma unroll
        for (int j = 0; j < TN; ++j) {
            int k = n0 + tx * TN + j;
            p += v[k] * tanhf(acc[i][j] + g_h2[b * H + k]);
        }
        atomicAdd(&rowsum[m], p);
    }
    __syncthreads();
    if (tid < BM) atomicAdd(&g_energy[m0 + tid], rowsum[tid]);
}

// ---------------------------------------------------------------------------
// Kernel 2: masked softmax over S per batch column; also zeroes d_out row
// one block (256 threads) per b
// ---------------------------------------------------------------------------
__global__ void k_softmax(const int* __restrict__ mask, float* __restrict__ out) {
    __shared__ float buf[S];
    __shared__ float redm[8];
    __shared__ float reds[8];

    const int b   = blockIdx.x;
    const int tid = threadIdx.x;

    float lmax = -3.4e38f;
    for (int s = tid; s < S; s += 256) {
        float e = mask[s * B + b] ? g_energy[s * B + b] : -1e10f;
        buf[s] = e;
        lmax = fmaxf(lmax, e);
    }
    #pragma unroll
    for (int o = 16; o; o >>= 1) lmax = fmaxf(lmax, __shfl_xor_sync(0xffffffffu, lmax, o));
    if ((tid & 31) == 0) redm[tid >> 5] = lmax;
    __syncthreads();
    if (tid == 0) {
        float m = redm[0];
        #pragma unroll
        for (int w = 1; w < 8; ++w) m = fmaxf(m, redm[w]);
        redm[0] = m;
    }
    __syncthreads();
    const float gmax = redm[0];

    float lsum = 0.0f;
    for (int s = tid; s < S; s += 256) {
        float ex = __expf(buf[s] - gmax);
        buf[s] = ex;
        lsum += ex;
    }
    #pragma unroll
    for (int o = 16; o; o >>= 1) lsum += __shfl_xor_sync(0xffffffffu, lsum, o);
    if ((tid & 31) == 0) reds[tid >> 5] = lsum;
    __syncthreads();
    if (tid == 0) {
        float sum = 0.0f;
        #pragma unroll
        for (int w = 0; w < 8; ++w) sum += reds[w];
        reds[0] = 1.0f / sum;
    }
    __syncthreads();
    const float inv = reds[0];

    for (int s = tid; s < S; s += 256)
        g_energy[s * B + b] = buf[s] * inv;       // now holds attn

    // zero this batch's output row (d_out is poisoned; k_ctx accumulates atomically)
    for (int i = tid; i < H; i += 256) out[b * H + i] = 0.0f;
}

// ---------------------------------------------------------------------------
// Kernel 3: context[b,h] = sum_s attn[s,b] * hs[s,b,h]
// grid (B, H/256, S_splits=8); atomicAdd into out
// ---------------------------------------------------------------------------
__global__ void k_ctx(const float* __restrict__ hs, float* __restrict__ out) {
    const int b  = blockIdx.x;
    const int h  = blockIdx.y * 256 + threadIdx.x;
    const int s0 = blockIdx.z * (S / 8);

    float acc = 0.0f;
    #pragma unroll 8
    for (int s = s0; s < s0 + S / 8; ++s) {
        float a = g_energy[s * B + b];
        acc = fmaf(a, __ldg(&hs[((size_t)s * B + b) * H + h]), acc);
    }
    atomicAdd(&out[b * H + h], acc);
}

// ---------------------------------------------------------------------------
// launch
// inputs: 0 hidden (1,B,H) f32 | 1 hidden_sequence (S,B,H) f32 | 2 input_masks (S,B) int32
//         3 W1 (H,H) f32 | 4 b1 (H) f32 | 5 W2 (H,H) f32 | 6 b2 (H) f32 | 7 v (H) f32
// output: context (1,B,H) f32
// ---------------------------------------------------------------------------
extern "C" void kernel_launch(void* const* d_in, const int* in_sizes, int n_in,
                              void* d_out, int out_size) {
    const float* hidden = (const float*)d_in[0];
    const float* hs     = (const float*)d_in[1];
    const int*   mask   = (const int*)d_in[2];   // bool promoted to int32 (assumed)
    const float* W1     = (const float*)d_in[3];
    const float* b1     = (const float*)d_in[4];
    const float* W2     = (const float*)d_in[5];
    const float* b2     = (const float*)d_in[6];
    const float* v      = (const float*)d_in[7];
    float*       out    = (float*)d_out;

    // 1) zero energy accumulator
    kz_zero_energy<<<R / 256, 256>>>();

    // 2) h2 = hidden·W2^T + b1 + b2  (one warp per output, 8 warps/block)
    k_h2<<<(B * H) / 8, 256>>>(hidden, W2, b1, b2);

    // 3) fused energy GEMM: grid.x = k-tiles, grid.y = row-tiles
    dim3 g1(H / BN, R / BM);
    k_energy_gemm<<<g1, 256>>>(hs, W1, v);

    // 4) masked softmax per batch + zero out
    k_softmax<<<B, 256>>>(mask, out);

    // 5) context accumulation
    dim3 g3(B, H / 256, 8);
    k_ctx<<<g3, 256>>>(hs, out);
}